// round 9
// baseline (speedup 1.0000x reference)
#include <cuda_runtime.h>
#include <cuda_bf16.h>
#include <math.h>

// Problem constants: V=32000, H=512, TS=TT=48, B=64, PAD=0
// Inputs (metadata order):
//  0 src(48,64)i32  1 tgt(48,64)i32  2 emb(32000,512)
//  3 enc0_Wih(1536,512) 4 enc0_bih 5 enc0_Ur 6 enc0_Uz 7 enc0_Un 8 enc0_bn
//  9 enc1_Wih(1536,1024) 10 enc1_bih 11 enc1_Ur 12 enc1_Uz 13 enc1_Un 14 enc1_bn
// 15 fc_init_w(512,1024) 16 fc_init_b 17 Wa(1024,512) 18 attn_combine_w(512,1536)
// 19 dec_Wih(1536,1024) 20 dec_bih 21 dec_Ur 22 dec_Uz 23 dec_Un 24 dec_bn
// 25 out_w(32000,512)
// Output: logits (48,64,32000) f32

#define NTB (48*64)            // 3072 time-batch rows

// ---------------- scratch (static device globals; no allocation) -------------
__device__ __align__(256) float g_src_emb[NTB*512];
__device__ __align__(256) float g_tgt_emb[NTB*512];
__device__ __align__(256) float g_xp0[NTB*1536];
__device__ __align__(256) float g_l0 [NTB*1024];
__device__ __align__(256) float g_xp1[NTB*1536];
__device__ __align__(256) float g_henc[NTB*1024];
__device__ __align__(256) float g_hw [NTB*512];
__device__ __align__(256) float g_xpx[NTB*1536];
__device__ __align__(256) float g_hts[NTB*512];
__device__ __align__(256) float g_uc0[1536*512];
__device__ __align__(256) float g_uc1[1536*512];
__device__ __align__(256) float g_dw [3072*512];   // [WihH(1536); dUr;dUz;dUn]
__device__ __align__(256) float g_wat[512*1024];   // Wa transposed (n,k)
__device__ __align__(256) float g_est[128*512];    // encoder state: rows0-63 fwd, 64-127 bwd
__device__ __align__(256) float g_dst[128*512];    // decoder state: rows0-63 ht, 64-127 h
__device__ __align__(256) float g_hfhb[64*1024];
__device__ __align__(256) float g_P [128*1536];    // encoder per-step U-projections
__device__ __align__(256) float g_G [2*64*1536];   // decoder: G0=ht@WihH^T, G1=h@Ucat^T
__device__ __align__(256) float g_cc[64*1536];     // [h | ctx]
__device__ __align__(256) float g_cp[4*64*512];    // split-K partials for combine

// ---------------- helpers ----------------------------------------------------
__device__ __forceinline__ unsigned long long fma2(unsigned long long a,
                                                   unsigned long long b,
                                                   unsigned long long c){
  unsigned long long d;
  asm("fma.rn.f32x2 %0, %1, %2, %3;" : "=l"(d) : "l"(a), "l"(b), "l"(c));
  return d;
}
__device__ __forceinline__ unsigned long long pack2(float x, float y){
  unsigned long long d;
  asm("mov.b64 %0, {%1, %2};" : "=l"(d) : "f"(x), "f"(y));
  return d;
}
__device__ __forceinline__ float2 unpack2(unsigned long long v){
  float2 r;
  asm("mov.b64 {%0, %1}, %2;" : "=f"(r.x), "=f"(r.y) : "l"(v));
  return r;
}
__device__ __forceinline__ float sigmf(float x){ return 1.f/(1.f+__expf(-x)); }

// ---------------- embedding gather -------------------------------------------
__global__ void k_gather(const int* __restrict__ src, const int* __restrict__ tgt,
                         const float* __restrict__ emb,
                         float* __restrict__ se, float* __restrict__ te){
  int idx = blockIdx.x;                 // 0..6143
  int is_src = idx < NTB;
  int i = is_src ? idx : idx - NTB;
  int token = is_src ? src[i] : tgt[i];
  const float4* erow = (const float4*)(emb + (size_t)token*512);
  float4* orow = (float4*)((is_src ? se : te) + (size_t)i*512);
  orow[threadIdx.x] = erow[threadIdx.x]; // 128 threads x float4 = 512 floats
}

// ---------------- weight prep ------------------------------------------------
__global__ void k_prep(const float* e0Ur, const float* e0Uz, const float* e0Un,
                       const float* e1Ur, const float* e1Uz, const float* e1Un,
                       const float* dUr, const float* dUz, const float* dUn,
                       const float* dWih, const float* Wa,
                       float* uc0, float* uc1, float* dw, float* wat){
  const int n1 = 1536*512;         // 786432 per ucat
  const int n2 = 3072*512;         // 1572864 dw
  const int n3 = 512*1024;         // 524288 wat
  int total = 2*n1 + n2 + n3;
  for (int i = blockIdx.x*blockDim.x + threadIdx.x; i < total;
       i += gridDim.x*blockDim.x){
    if (i < n1){
      int g = i / 262144, r = i % 262144;
      uc0[i] = g==0 ? e0Ur[r] : (g==1 ? e0Uz[r] : e0Un[r]);
    } else if (i < 2*n1){
      int j = i - n1; int g = j / 262144, r = j % 262144;
      uc1[j] = g==0 ? e1Ur[r] : (g==1 ? e1Uz[r] : e1Un[r]);
    } else if (i < 2*n1 + n2){
      int j = i - 2*n1; int row = j >> 9, k = j & 511;
      float v;
      if      (row < 1536) v = dWih[(size_t)row*1024 + 512 + k];
      else if (row < 2048) v = dUr[(row-1536)*512 + k];
      else if (row < 2560) v = dUz[(row-2048)*512 + k];
      else                 v = dUn[(row-2560)*512 + k];
      dw[j] = v;
    } else {
      int j = i - 2*n1 - n2; int nn = j >> 10, k = j & 1023;
      wat[j] = Wa[(size_t)k*512 + nn];
    }
  }
}

__global__ void k_zero(float* p, int n){
  int i = blockIdx.x*blockDim.x + threadIdx.x;
  if (i < n) p[i] = 0.f;
}

// ---------------- big GEMM: C(MxN) = act(scale*A(M,K)@W(N,K)^T + bias) -------
// grid = (N/128, M/128), 256 threads, 8x8 per thread via packed f32x2 FFMA.
__global__ __launch_bounds__(256) void k_gemm_big(
    const float* __restrict__ A, int lda,
    const float* __restrict__ W, int ldw,
    const float* __restrict__ bias,
    float* __restrict__ C, int ldc,
    int K, float scale, int act)
{
  __shared__ __align__(16) float As[16][136];
  __shared__ __align__(16) float Bs[16][136];
  int t = threadIdx.x;
  int m0 = blockIdx.y * 128, n0 = blockIdx.x * 128;
  int ar = t >> 1, ak = (t & 1) * 8;
  const float* Ap = A + (size_t)(m0 + ar)*lda + ak;
  const float* Wp = W + (size_t)(n0 + ar)*ldw + ak;
  int tx = t & 15, ty = t >> 4;
  int cm = ty * 8, cn = tx * 8;
  unsigned long long acc[8][4];
#pragma unroll
  for (int i=0;i<8;i++)
#pragma unroll
    for (int j=0;j<4;j++) acc[i][j] = 0ull;

  for (int k0 = 0; k0 < K; k0 += 16){
    float4 a0 = *(const float4*)(Ap + k0);
    float4 a1 = *(const float4*)(Ap + k0 + 4);
    float4 w0 = *(const float4*)(Wp + k0);
    float4 w1 = *(const float4*)(Wp + k0 + 4);
    __syncthreads();
    As[ak+0][ar]=a0.x; As[ak+1][ar]=a0.y; As[ak+2][ar]=a0.z; As[ak+3][ar]=a0.w;
    As[ak+4][ar]=a1.x; As[ak+5][ar]=a1.y; As[ak+6][ar]=a1.z; As[ak+7][ar]=a1.w;
    Bs[ak+0][ar]=w0.x; Bs[ak+1][ar]=w0.y; Bs[ak+2][ar]=w0.z; Bs[ak+3][ar]=w0.w;
    Bs[ak+4][ar]=w1.x; Bs[ak+5][ar]=w1.y; Bs[ak+6][ar]=w1.z; Bs[ak+7][ar]=w1.w;
    __syncthreads();
#pragma unroll
    for (int kk=0; kk<16; kk++){
      float4 af0 = *(const float4*)&As[kk][cm];
      float4 af1 = *(const float4*)&As[kk][cm+4];
      float4 bf0 = *(const float4*)&Bs[kk][cn];
      float4 bf1 = *(const float4*)&Bs[kk][cn+4];
      unsigned long long bp0 = pack2(bf0.x, bf0.y);
      unsigned long long bp1 = pack2(bf0.z, bf0.w);
      unsigned long long bp2 = pack2(bf1.x, bf1.y);
      unsigned long long bp3 = pack2(bf1.z, bf1.w);
      float am[8] = {af0.x,af0.y,af0.z,af0.w,af1.x,af1.y,af1.z,af1.w};
#pragma unroll
      for (int i=0;i<8;i++){
        unsigned long long ap = pack2(am[i], am[i]);
        acc[i][0] = fma2(ap, bp0, acc[i][0]);
        acc[i][1] = fma2(ap, bp1, acc[i][1]);
        acc[i][2] = fma2(ap, bp2, acc[i][2]);
        acc[i][3] = fma2(ap, bp3, acc[i][3]);
      }
    }
  }
#pragma unroll
  for (int i=0;i<8;i++){
    float* crow = C + (size_t)(m0+cm+i)*ldc + n0 + cn;
#pragma unroll
    for (int j=0;j<4;j++){
      float2 v = unpack2(acc[i][j]);
      float x0 = v.x*scale, x1 = v.y*scale;
      if (bias){ x0 += bias[n0+cn+2*j]; x1 += bias[n0+cn+2*j+1]; }
      if (act){ x0 = tanhf(x0); x1 = tanhf(x1); }
      *(float2*)(crow + 2*j) = make_float2(x0, x1);
    }
  }
}

// ---------------- small GEMM: 64x32 tiles, groups + m-tiles + split-K --------
// grid = (N/32, groups, M/64); effective A += gy*gsA, W += gy*gsW, C += gy*gsC,
// k range = [gy*kgs, gy*kgs + K).
__global__ __launch_bounds__(256) void k_gemm_small(
    const float* __restrict__ A, int lda, long long gsA,
    const float* __restrict__ W, int ldw, long long gsW,
    const float* __restrict__ bias,
    float* __restrict__ C, int ldc, long long gsC,
    int K, int kgs, float scale, int act)
{
  __shared__ __align__(16) float As[16][68];
  __shared__ __align__(16) float Bs[16][36];
  int t = threadIdx.x;
  int n0 = blockIdx.x * 32;
  int gy = blockIdx.y;
  int m0 = blockIdx.z * 64;
  int kstart = gy * kgs;
  int ar = t & 63, ak = (t >> 6) << 2;
  int wr = t & 31, wk = ((t & 127) >> 5) << 2;
  const float* Ap = A + (size_t)gy*gsA + (size_t)(m0 + ar)*lda + kstart + ak;
  const float* Wp = W + (size_t)gy*gsW + (size_t)(n0 + wr)*ldw + kstart + wk;
  int tx = t & 15, ty = t >> 4;
  int cm = ty * 4, cn = tx * 2;
  float acc[4][2] = {{0.f,0.f},{0.f,0.f},{0.f,0.f},{0.f,0.f}};
  for (int k0 = 0; k0 < K; k0 += 16){
    float4 av = *(const float4*)(Ap + k0);
    float4 wv = make_float4(0.f,0.f,0.f,0.f);
    if (t < 128) wv = *(const float4*)(Wp + k0);
    __syncthreads();
    As[ak+0][ar]=av.x; As[ak+1][ar]=av.y; As[ak+2][ar]=av.z; As[ak+3][ar]=av.w;
    if (t < 128){ Bs[wk+0][wr]=wv.x; Bs[wk+1][wr]=wv.y; Bs[wk+2][wr]=wv.z; Bs[wk+3][wr]=wv.w; }
    __syncthreads();
#pragma unroll
    for (int kk=0; kk<16; kk++){
      float4 af = *(const float4*)&As[kk][cm];
      float2 bf = *(const float2*)&Bs[kk][cn];
      acc[0][0] += af.x*bf.x; acc[0][1] += af.x*bf.y;
      acc[1][0] += af.y*bf.x; acc[1][1] += af.y*bf.y;
      acc[2][0] += af.z*bf.x; acc[2][1] += af.z*bf.y;
      acc[3][0] += af.w*bf.x; acc[3][1] += af.w*bf.y;
    }
  }
  float* Cg = C + (size_t)gy*gsC;
#pragma unroll
  for (int i=0;i<4;i++){
#pragma unroll
    for (int j=0;j<2;j++){
      float v = acc[i][j]*scale;
      if (bias) v += bias[n0+cn+j];
      if (act) v = tanhf(v);
      Cg[(size_t)(m0+cm+i)*ldc + n0 + cn + j] = v;
    }
  }
}

// ---------------- encoder elementwise GRU step -------------------------------
// grid 128 blocks (row r: 0-63 fwd b, 64-127 bwd b), 512 threads (j).
__global__ void k_enc_elem(const float* __restrict__ xp, const float* __restrict__ P,
                           const float* __restrict__ bn, float* __restrict__ state,
                           float* __restrict__ out, int t){
  int r = blockIdx.x, j = threadIdx.x;
  int b = r & 63;
  int fwd = (r < 64);
  int tpos = fwd ? t : 47 - t;
  const float* xrow = xp + ((size_t)tpos*64 + b)*1536;
  const float* prow = P + (size_t)r*1536;
  float h  = state[r*512 + j];
  float rg = sigmf(xrow[j]       + prow[j]);
  float zg = sigmf(xrow[512 + j] + prow[512 + j]);
  float ng = tanhf(xrow[1024+ j] + rg*(prow[1024 + j] + bn[j]));
  float hn = (1.f - zg)*ng + zg*h;
  state[r*512 + j] = hn;
  out[((size_t)tpos*64 + b)*1024 + (fwd ? 0 : 512) + j] = hn;
}

// ---------------- hf|hb concat -----------------------------------------------
__global__ void k_hfhb(const float* __restrict__ est, float* __restrict__ hfhb){
  int i = blockIdx.x*blockDim.x + threadIdx.x;   // 65536
  int b = i >> 10, k = i & 1023;
  hfhb[i] = (k < 512) ? est[b*512 + k] : est[(64 + b)*512 + (k - 512)];
}

// ---------------- decoder: GRU elementwise + attention (per-batch block) -----
__global__ void k_dec_attn(const float* __restrict__ xpx, const float* __restrict__ G,
                           const float* __restrict__ bn, float* __restrict__ dst,
                           const float* __restrict__ hw, const float* __restrict__ henc,
                           const int* __restrict__ src, float* __restrict__ cc, int t){
  int b = blockIdx.x, tid = threadIdx.x;
  __shared__ float hsm[512];
  __shared__ float ssm[48];
  __shared__ float sinv;
  const float* xrow = xpx + ((size_t)t*64 + b)*1536;
  const float* g0 = G + (size_t)b*1536;           // ht @ WihH^T
  const float* g1 = G + (size_t)(64 + b)*1536;    // h  @ [Ur;Uz;Un]^T
  for (int j = tid; j < 512; j += 256){
    float rg = sigmf(xrow[j]        + g0[j]        + g1[j]);
    float zg = sigmf(xrow[512 + j]  + g0[512 + j]  + g1[512 + j]);
    float ng = tanhf(xrow[1024 + j] + g0[1024 + j] + rg*(g1[1024 + j] + bn[j]));
    float h  = dst[(size_t)(64 + b)*512 + j];
    float hn = (1.f - zg)*ng + zg*h;
    dst[(size_t)(64 + b)*512 + j] = hn;
    hsm[j] = hn;
    cc[(size_t)b*1536 + j] = hn;
  }
  __syncthreads();
  int w = tid >> 5, lane = tid & 31;
  for (int tp = w; tp < 48; tp += 8){
    const float* hwrow = hw + ((size_t)tp*64 + b)*512;
    float s = 0.f;
    for (int j = lane; j < 512; j += 32) s += hsm[j]*hwrow[j];
#pragma unroll
    for (int o = 16; o; o >>= 1) s += __shfl_xor_sync(0xffffffffu, s, o);
    if (lane == 0) ssm[tp] = (src[tp*64 + b] == 0) ? -1e9f : s;
  }
  __syncthreads();
  if (tid == 0){
    float mx = -1e30f;
    for (int i = 0; i < 48; i++) mx = fmaxf(mx, ssm[i]);
    float sum = 0.f;
    for (int i = 0; i < 48; i++){ float e = __expf(ssm[i]-mx); ssm[i] = e; sum += e; }
    sinv = 1.f/sum;
  }
  __syncthreads();
  for (int d = tid; d < 1024; d += 256){
    float accv = 0.f;
#pragma unroll 4
    for (int tp = 0; tp < 48; tp++)
      accv += ssm[tp]*henc[((size_t)tp*64 + b)*1024 + d];
    cc[(size_t)b*1536 + 512 + d] = accv*sinv;
  }
}

// ---------------- combine split-K reduce + tanh -> ht, Hts[t] ----------------
__global__ void k_comb_reduce(const float* __restrict__ cp, float* __restrict__ dst,
                              float* __restrict__ hts, int t){
  int i = blockIdx.x*blockDim.x + threadIdx.x;   // 32768 = 64*512
  float v = cp[i] + cp[32768 + i] + cp[2*32768 + i] + cp[3*32768 + i];
  v = tanhf(v);
  dst[i] = v;                                     // ht rows 0..63
  hts[(size_t)t*32768 + i] = v;
}

// =============================================================================
extern "C" void kernel_launch(void* const* d_in, const int* in_sizes, int n_in,
                              void* d_out, int out_size){
  const int*   src  = (const int*)  d_in[0];
  const int*   tgt  = (const int*)  d_in[1];
  const float* emb  = (const float*)d_in[2];
  const float* e0Wih=(const float*)d_in[3];  const float* e0bih=(const float*)d_in[4];
  const float* e0Ur =(const float*)d_in[5];  const float* e0Uz =(const float*)d_in[6];
  const float* e0Un =(const float*)d_in[7];  const float* e0bn =(const float*)d_in[8];
  const float* e1Wih=(const float*)d_in[9];  const float* e1bih=(const float*)d_in[10];
  const float* e1Ur =(const float*)d_in[11]; const float* e1Uz =(const float*)d_in[12];
  const float* e1Un =(const float*)d_in[13]; const float* e1bn =(const float*)d_in[14];
  const float* fcw  =(const float*)d_in[15]; const float* fcb  =(const float*)d_in[16];
  const float* Wa   =(const float*)d_in[17]; const float* acw  =(const float*)d_in[18];
  const float* dWih =(const float*)d_in[19]; const float* dbih =(const float*)d_in[20];
  const float* dUr  =(const float*)d_in[21]; const float* dUz  =(const float*)d_in[22];
  const float* dUn  =(const float*)d_in[23]; const float* dbn  =(const float*)d_in[24];
  const float* outw =(const float*)d_in[25];
  float* out = (float*)d_out;

  float *se,*te,*xp0,*l0,*xp1,*henc,*hw,*xpx,*hts,*uc0,*uc1,*dw,*wat,*est,*dst,*hfhb,*P,*G,*cc,*cp;
  cudaGetSymbolAddress((void**)&se,  g_src_emb);
  cudaGetSymbolAddress((void**)&te,  g_tgt_emb);
  cudaGetSymbolAddress((void**)&xp0, g_xp0);
  cudaGetSymbolAddress((void**)&l0,  g_l0);
  cudaGetSymbolAddress((void**)&xp1, g_xp1);
  cudaGetSymbolAddress((void**)&henc,g_henc);
  cudaGetSymbolAddress((void**)&hw,  g_hw);
  cudaGetSymbolAddress((void**)&xpx, g_xpx);
  cudaGetSymbolAddress((void**)&hts, g_hts);
  cudaGetSymbolAddress((void**)&uc0, g_uc0);
  cudaGetSymbolAddress((void**)&uc1, g_uc1);
  cudaGetSymbolAddress((void**)&dw,  g_dw);
  cudaGetSymbolAddress((void**)&wat, g_wat);
  cudaGetSymbolAddress((void**)&est, g_est);
  cudaGetSymbolAddress((void**)&dst, g_dst);
  cudaGetSymbolAddress((void**)&hfhb,g_hfhb);
  cudaGetSymbolAddress((void**)&P,   g_P);
  cudaGetSymbolAddress((void**)&G,   g_G);
  cudaGetSymbolAddress((void**)&cc,  g_cc);
  cudaGetSymbolAddress((void**)&cp,  g_cp);

  // ---- prep: gathers, weight concat/transpose ----
  k_gather<<<2*NTB, 128>>>(src, tgt, emb, se, te);
  k_prep<<<1792, 256>>>(e0Ur,e0Uz,e0Un, e1Ur,e1Uz,e1Un, dUr,dUz,dUn, dWih, Wa,
                        uc0, uc1, dw, wat);

  // ---- encoder layer 0 ----
  k_gemm_big<<<dim3(12,24), 256>>>(se, 512, e0Wih, 512, e0bih, xp0, 1536, 512, 1.f, 0);
  k_zero<<<256, 256>>>(est, 128*512);
  for (int t = 0; t < 48; t++){
    k_gemm_small<<<dim3(48,1,2), 256>>>(est,512,0LL, uc0,512,0LL, (const float*)nullptr,
                                        P,1536,0LL, 512, 0, 1.f, 0);
    k_enc_elem<<<128, 512>>>(xp0, P, e0bn, est, l0, t);
  }
  // ---- encoder layer 1 ----
  k_gemm_big<<<dim3(12,24), 256>>>(l0, 1024, e1Wih, 1024, e1bih, xp1, 1536, 1024, 1.f, 0);
  k_zero<<<256, 256>>>(est, 128*512);
  for (int t = 0; t < 48; t++){
    k_gemm_small<<<dim3(48,1,2), 256>>>(est,512,0LL, uc1,512,0LL, (const float*)nullptr,
                                        P,1536,0LL, 512, 0, 1.f, 0);
    k_enc_elem<<<128, 512>>>(xp1, P, e1bn, est, henc, t);
  }
  // ---- decoder init: h0 = tanh([hf|hb]@fcw^T + fcb), ht0 = 0 ----
  k_hfhb<<<256, 256>>>(est, hfhb);
  k_zero<<<128, 256>>>(dst, 64*512);
  k_gemm_small<<<dim3(16,1,1), 256>>>(hfhb,1024,0LL, fcw,1024,0LL, fcb,
                                      dst + 64*512, 512, 0LL, 1024, 0, 1.f, 1);
  // ---- batched attention precomputes ----
  k_gemm_big<<<dim3(4,24), 256>>>(henc, 1024, wat, 1024, (const float*)nullptr,
                                  hw, 512, 1024, 0.03125f, 0);           // scale=1/sqrt(1024)
  k_gemm_big<<<dim3(12,24), 256>>>(te, 512, dWih, 1024, dbih, xpx, 1536, 512, 1.f, 0);

  // ---- decoder scan ----
  for (int t = 0; t < 48; t++){
    // G0 = ht@WihH^T (rows 0-1535 of dw), G1 = h@[Ur;Uz;Un]^T (rows 1536-3071)
    k_gemm_small<<<dim3(48,2,1), 256>>>(dst,512,(long long)64*512,
                                        dw,512,(long long)1536*512, (const float*)nullptr,
                                        G,1536,(long long)64*1536, 512, 0, 1.f, 0);
    k_dec_attn<<<64, 256>>>(xpx, G, dbn, dst, hw, henc, src, cc, t);
    // combine: [h|ctx](64x1536) @ acw(512x1536)^T, split-K x4 partials
    k_gemm_small<<<dim3(16,4,1), 256>>>(cc,1536,0LL, acw,1536,0LL, (const float*)nullptr,
                                        cp,512,(long long)64*512, 384, 384, 1.f, 0);
    k_comb_reduce<<<128, 256>>>(cp, dst, hts, t);
  }

  // ---- logits: (3072,512) @ out_w(32000,512)^T ----
  k_gemm_big<<<dim3(250,24), 256>>>(hts, 512, outw, 512, (const float*)nullptr,
                                    out, 32000, 512, 1.f, 0);
}